// round 8
// baseline (speedup 1.0000x reference)
#include <cuda_runtime.h>
#include <math.h>

// MatchLoss: per src point (16384x3 f32), is the 2nd-nearest tgt within 1e-3?
// mv = (pd<1e-3)+1e-7 with pd = ||src - tgt_2nd + 1e-6||; out = log(1+sum(exp(mv))).
// mv takes only two values -> out = log(1 + (N-m)*e^eps + m*e^(1+eps)), m = match count.
// Fixed-radius search via spatial hash (cell = 1.1e-3): any tgt with d < 1.05e-3
// lies in the 27-cell neighborhood; exact pd recomputed from candidate coords.
// Single fused kernel: clear -> barrier -> build -> barrier -> query -> finalize.
#define NPTS      16384
#define HBITS     16
#define HSIZE     (1 << HBITS)
#define THREADS   256
#define NB        (NPTS / THREADS)     // 64 blocks, one wave, all co-resident

#define EPS_F     1e-7f
#define CELL_F    1.1e-3f
#define INV_CELL  (1.0f / CELL_F)
#define R2CUT     (1.05e-3f * 1.05e-3f)   // gate for candidate 2nd-NN
#define RAD2      (1e-3f * 1e-3f)         // pd^2 threshold
#define BIG       3.402823466e+38f

__device__ int       g_head[HSIZE];
__device__ int       g_next[NPTS];
__device__ long long g_ckey[NPTS];
__device__ int       g_match;
__device__ int       g_bar  = 0;   // phase barrier counter (restored each launch)
__device__ int       g_exit = 0;   // exit counter (restored each launch)

__device__ __forceinline__ unsigned int cell_hash(int cx, int cy, int cz) {
    unsigned int h = (unsigned int)(cx * 73856093) ^
                     (unsigned int)(cy * 19349663) ^
                     (unsigned int)(cz * 83492791);
    return h & (HSIZE - 1);
}

__device__ __forceinline__ long long cell_key(int cx, int cy, int cz) {
    return (((long long)(cx + (1 << 20))) << 42) |
           (((long long)(cy + (1 << 20))) << 21) |
            ((long long)(cz + (1 << 20)));
}

// Grid-wide barrier: all NB blocks are co-resident (single wave), so spinning
// is deadlock-free. Counter accumulates across phases; restored on exit.
__device__ __forceinline__ void grid_barrier(int target) {
    __syncthreads();
    if (threadIdx.x == 0) {
        __threadfence();
        atomicAdd(&g_bar, 1);
        while (*(volatile int*)&g_bar < target) { }
        __threadfence();
    }
    __syncthreads();
}

__global__ __launch_bounds__(THREADS)
void ml_fused_kernel(const float* __restrict__ src, const float* __restrict__ tgt,
                     float* __restrict__ out) {
    __shared__ int swarp[THREADS / 32];
    const int tid  = threadIdx.x;
    const int lane = tid & 31;
    const int warp = tid >> 5;
    const int i = blockIdx.x * THREADS + tid;   // 0..16383

    // ---- Phase A: clear hash heads + match counter ----
    #pragma unroll
    for (int r = 0; r < HSIZE / NPTS; ++r)
        g_head[i + r * NPTS] = -1;
    if (i == 0) g_match = 0;

    grid_barrier(NB);

    // ---- Phase B: insert tgt points ----
    {
        const float x = tgt[3 * i + 0], y = tgt[3 * i + 1], z = tgt[3 * i + 2];
        const int cx = (int)floorf(x * INV_CELL);
        const int cy = (int)floorf(y * INV_CELL);
        const int cz = (int)floorf(z * INV_CELL);
        g_ckey[i] = cell_key(cx, cy, cz);
        g_next[i] = atomicExch(&g_head[cell_hash(cx, cy, cz)], i);
    }

    grid_barrier(2 * NB);

    // ---- Phase C: query src points over 27-cell neighborhood ----
    const float px = src[3 * i + 0], py = src[3 * i + 1], pz = src[3 * i + 2];
    const int cx = (int)floorf(px * INV_CELL);
    const int cy = (int)floorf(py * INV_CELL);
    const int cz = (int)floorf(pz * INV_CELL);

    float d1 = BIG, d2 = BIG;          // top-2 squared distances
    float q2x = 0, q2y = 0, q2z = 0;   // 2nd-best coords
    float q1x = 0, q1y = 0, q1z = 0;

    #pragma unroll
    for (int dx = -1; dx <= 1; ++dx)
    #pragma unroll
    for (int dy = -1; dy <= 1; ++dy)
    #pragma unroll
    for (int dz = -1; dz <= 1; ++dz) {
        const int ccx = cx + dx, ccy = cy + dy, ccz = cz + dz;
        const long long pkey = cell_key(ccx, ccy, ccz);
        for (int e = g_head[cell_hash(ccx, ccy, ccz)]; e >= 0; e = g_next[e]) {
            if (g_ckey[e] != pkey) continue;   // hash collision: skip foreign cell
            const float tx = tgt[3 * e + 0], ty = tgt[3 * e + 1], tz = tgt[3 * e + 2];
            const float ex = px - tx, ey = py - ty, ez = pz - tz;
            const float dd = fmaf(ex, ex, fmaf(ey, ey, ez * ez));
            if (dd < d2) {
                if (dd < d1) {
                    d2 = d1; q2x = q1x; q2y = q1y; q2z = q1z;
                    d1 = dd; q1x = tx;  q1y = ty;  q1z = tz;
                } else {
                    d2 = dd; q2x = tx;  q2y = ty;  q2z = tz;
                }
            }
        }
    }

    int m = 0;
    if (d2 <= R2CUT) {
        // exact reference pd: componentwise +1e-6 before the norm
        const float ex = px - q2x + 1e-6f;
        const float ey = py - q2y + 1e-6f;
        const float ez = pz - q2z + 1e-6f;
        if (fmaf(ex, ex, fmaf(ey, ey, ez * ez)) < RAD2) m = 1;
    }

    // Integer block reduce (deterministic), then one atomic per block
    #pragma unroll
    for (int o = 16; o > 0; o >>= 1)
        m += __shfl_down_sync(0xFFFFFFFFu, m, o);
    if (lane == 0) swarp[warp] = m;
    __syncthreads();

    if (tid == 0) {
        int bs = 0;
        #pragma unroll
        for (int w = 0; w < THREADS / 32; ++w) bs += swarp[w];
        if (bs) atomicAdd(&g_match, bs);
        __threadfence();
        // Last block to exit finalizes and restores barrier state. Safe:
        // every block increments g_exit only after passing its final spin,
        // so resetting g_bar cannot strand a spinner.
        const int e = atomicAdd(&g_exit, 1);
        if (e == NB - 1) {
            const int mm = *(volatile int*)&g_match;
            const float S = (float)(NPTS - mm) * expf(EPS_F)
                          + (float)mm * expf(1.0f + EPS_F);
            out[0] = logf(1.0f + S);   // softplus(logsumexp(mv))
            g_bar  = 0;                // restore for next graph replay
            g_exit = 0;
            __threadfence();
        }
    }
}

extern "C" void kernel_launch(void* const* d_in, const int* in_sizes, int n_in,
                              void* d_out, int out_size) {
    const float* src = (const float*)d_in[0];  // src_coords [16384, 3]
    const float* tgt = (const float*)d_in[1];  // tgt_coords [16384, 3]
    float* out = (float*)d_out;
    ml_fused_kernel<<<NB, THREADS>>>(src, tgt, out);
}

// round 9
// speedup vs baseline: 2.0174x; 2.0174x over previous
#include <cuda_runtime.h>
#include <math.h>

// MatchLoss: per src point (16384x3 f32), is the 2nd-nearest tgt within 1e-3?
// mv = (pd<1e-3)+1e-7, pd = ||src - tgt_2nd + 1e-6||; out = log(1+sum(exp(mv)))
//    = log(1 + (N-m)*e^eps + m*e^(1+eps)),  m = match count.
// Fixed-radius search via spatial hash (cell = 1.1e-3). Single kernel:
// insert (gen-stamped buckets, no clear) -> grid barrier -> query with 4
// threads/src (<=7 probe cells each, shfl merge). Exact fallback rescan for
// the (rare) case d2 <= R2CUT.
#define NPTS      16384
#define HBITS     16
#define HSIZE     (1 << HBITS)
#define QSPLIT    4
#define THREADS   256
#define NB        (NPTS * QSPLIT / THREADS)   // 256 blocks, single wave

#define EPS_F     1e-7f
#define CELL_F    1.1e-3f
#define INV_CELL  (1.0f / CELL_F)
#define R2CUT     (1.05e-3f * 1.05e-3f)
#define RAD2      (1e-3f * 1e-3f)
#define BIG       3.402823466e+38f

__device__ unsigned long long g_head[HSIZE];   // (gen<<14)|idx ; gen 0 = empty
__device__ int                g_next[NPTS];
__device__ long long          g_ckey[NPTS];
__device__ int                g_match;
__device__ int                g_bar  = 0;
__device__ int                g_exit = 0;
__device__ unsigned long long g_gen  = 1;      // bumped by last block each launch

__device__ __forceinline__ unsigned int cell_hash(int cx, int cy, int cz) {
    unsigned int h = (unsigned int)(cx * 73856093) ^
                     (unsigned int)(cy * 19349663) ^
                     (unsigned int)(cz * 83492791);
    return h & (HSIZE - 1);
}

__device__ __forceinline__ long long cell_key(int cx, int cy, int cz) {
    return (((long long)(cx + (1 << 20))) << 42) |
           (((long long)(cy + (1 << 20))) << 21) |
            ((long long)(cz + (1 << 20)));
}

__device__ __forceinline__ void grid_barrier(int target) {
    __syncthreads();
    if (threadIdx.x == 0) {
        __threadfence();
        atomicAdd(&g_bar, 1);
        while (*(volatile int*)&g_bar < target) { }
        __threadfence();
    }
    __syncthreads();
}

__global__ __launch_bounds__(THREADS)
void ml_fused_kernel(const float* __restrict__ src, const float* __restrict__ tgt,
                     float* __restrict__ out) {
    __shared__ int swarp[THREADS / 32];
    const int tid  = threadIdx.x;
    const int lane = tid & 31;
    const int warp = tid >> 5;
    const int g    = blockIdx.x * THREADS + tid;   // 0..65535
    const int q    = g >> 2;                        // src index, 4 lanes each
    const int half = g & 3;                         // probe-group 0..3

    const unsigned long long gen = g_gen;           // consistent: set pre-launch

    // ---- Phase B: insert tgt points (one lane per tgt; no table clear) ----
    if (half == 0) {
        const float x = tgt[3 * q + 0], y = tgt[3 * q + 1], z = tgt[3 * q + 2];
        const int cx = (int)floorf(x * INV_CELL);
        const int cy = (int)floorf(y * INV_CELL);
        const int cz = (int)floorf(z * INV_CELL);
        g_ckey[q] = cell_key(cx, cy, cz);
        const unsigned long long old =
            atomicExch(&g_head[cell_hash(cx, cy, cz)],
                       (gen << 14) | (unsigned long long)q);
        g_next[q] = ((old >> 14) == gen) ? (int)(old & 16383ULL) : -1;
    }
    if (g == 0) g_match = 0;

    grid_barrier(NB);

    // ---- Phase C: query; this lane handles probes [half*7, half*7+np) ----
    const float px = src[3 * q + 0], py = src[3 * q + 1], pz = src[3 * q + 2];
    const int cx = (int)floorf(px * INV_CELL);
    const int cy = (int)floorf(py * INV_CELL);
    const int cz = (int)floorf(pz * INV_CELL);

    const int p0 = half * 7;
    const int np = (half < 3) ? 7 : 6;

    // Batched, independent head loads (MLP ~ 7)
    unsigned long long heads[7];
    long long pkeys[7];
    #pragma unroll
    for (int j = 0; j < 7; ++j) {
        if (j < np) {
            const int p = p0 + j;
            const int ccx = cx + (p / 9) - 1;
            const int ccy = cy + ((p / 3) % 3) - 1;
            const int ccz = cz + (p % 3) - 1;
            pkeys[j] = cell_key(ccx, ccy, ccz);
            heads[j] = g_head[cell_hash(ccx, ccy, ccz)];
        }
    }

    float d1 = BIG, d2 = BIG;
    #pragma unroll
    for (int j = 0; j < 7; ++j) {
        if (j < np) {
            int e = ((heads[j] >> 14) == gen) ? (int)(heads[j] & 16383ULL) : -1;
            while (e >= 0) {
                if (g_ckey[e] == pkeys[j]) {
                    const float ex = px - tgt[3 * e + 0];
                    const float ey = py - tgt[3 * e + 1];
                    const float ez = pz - tgt[3 * e + 2];
                    const float dd = fmaf(ex, ex, fmaf(ey, ey, ez * ez));
                    d2 = fminf(d2, fmaxf(d1, dd));
                    d1 = fminf(d1, dd);
                }
                e = g_next[e];
            }
        }
    }

    // Merge top-2 values across the 4 lanes of this src point
    #pragma unroll
    for (int o = 1; o <= 2; o <<= 1) {
        const float o1 = __shfl_xor_sync(0xFFFFFFFFu, d1, o);
        const float o2 = __shfl_xor_sync(0xFFFFFFFFu, d2, o);
        d2 = fminf(fmaxf(d1, o1), fminf(d2, o2));
        d1 = fminf(d1, o1);
    }

    int m = 0;
    if (half == 0 && d2 <= R2CUT) {
        // Rare exact fallback: rescan all 27 cells tracking coords, apply
        // the reference pd test (componentwise +1e-6 before the norm).
        float e1 = BIG, e2 = BIG;
        float q1x = 0, q1y = 0, q1z = 0, q2x = 0, q2y = 0, q2z = 0;
        for (int p = 0; p < 27; ++p) {
            const int ccx = cx + (p / 9) - 1;
            const int ccy = cy + ((p / 3) % 3) - 1;
            const int ccz = cz + (p % 3) - 1;
            const long long pk = cell_key(ccx, ccy, ccz);
            unsigned long long hw = g_head[cell_hash(ccx, ccy, ccz)];
            int e = ((hw >> 14) == gen) ? (int)(hw & 16383ULL) : -1;
            while (e >= 0) {
                if (g_ckey[e] == pk) {
                    const float tx = tgt[3 * e + 0], ty = tgt[3 * e + 1], tz = tgt[3 * e + 2];
                    const float ex = px - tx, ey = py - ty, ez = pz - tz;
                    const float dd = fmaf(ex, ex, fmaf(ey, ey, ez * ez));
                    if (dd < e2) {
                        if (dd < e1) {
                            e2 = e1; q2x = q1x; q2y = q1y; q2z = q1z;
                            e1 = dd; q1x = tx;  q1y = ty;  q1z = tz;
                        } else {
                            e2 = dd; q2x = tx; q2y = ty; q2z = tz;
                        }
                    }
                }
                e = g_next[e];
            }
        }
        if (e2 <= R2CUT) {
            const float ex = px - q2x + 1e-6f;
            const float ey = py - q2y + 1e-6f;
            const float ez = pz - q2z + 1e-6f;
            if (fmaf(ex, ex, fmaf(ey, ey, ez * ez)) < RAD2) m = 1;
        }
    }

    // Deterministic integer reduction; one atomic per block
    #pragma unroll
    for (int o = 16; o > 0; o >>= 1)
        m += __shfl_down_sync(0xFFFFFFFFu, m, o);
    if (lane == 0) swarp[warp] = m;
    __syncthreads();

    if (tid == 0) {
        int bs = 0;
        #pragma unroll
        for (int w = 0; w < THREADS / 32; ++w) bs += swarp[w];
        if (bs) atomicAdd(&g_match, bs);
        __threadfence();
        // Last block to exit finalizes and restores state for graph replay.
        const int e = atomicAdd(&g_exit, 1);
        if (e == NB - 1) {
            const int mm = *(volatile int*)&g_match;
            const float S = (float)(NPTS - mm) * expf(EPS_F)
                          + (float)mm * expf(1.0f + EPS_F);
            out[0] = logf(1.0f + S);   // softplus(logsumexp(mv))
            g_bar  = 0;
            g_exit = 0;
            g_gen  = gen + 1;          // invalidates all buckets for next launch
            __threadfence();
        }
    }
}

extern "C" void kernel_launch(void* const* d_in, const int* in_sizes, int n_in,
                              void* d_out, int out_size) {
    const float* src = (const float*)d_in[0];  // src_coords [16384, 3]
    const float* tgt = (const float*)d_in[1];  // tgt_coords [16384, 3]
    float* out = (float*)d_out;
    ml_fused_kernel<<<NB, THREADS>>>(src, tgt, out);
}

// round 10
// speedup vs baseline: 2.9820x; 1.4781x over previous
#include <cuda_runtime.h>
#include <math.h>

// MatchLoss: per src point (16384x3 f32), is the 2nd-nearest tgt within 1e-3?
// mv = (pd<1e-3)+1e-7, pd = ||src - tgt_2nd + 1e-6||; out = log(1+sum(exp(mv)))
//    = log(1 + (N-m)*e^eps + m*e^(1+eps)),  m = match count.
// Spatial hash with cell = 2.1e-3 >= 2*r_eff: the radius ball fits in the
// 2x2x2 cell block picked by the point's half-cell position -> 8 probes/src.
// Single kernel: insert (gen-stamped buckets, no clear) -> grid barrier ->
// query with 4 threads/src (2 probe cells each, shfl merge). Exact fallback
// rescan for the (rare) case d2 <= R2CUT.
#define NPTS      16384
#define HBITS     16
#define HSIZE     (1 << HBITS)
#define QSPLIT    4
#define THREADS   256
#define NB        (NPTS * QSPLIT / THREADS)   // 256 blocks, single wave

#define EPS_F     1e-7f
#define CELL_F    2.1e-3f
#define INV_CELL  (1.0f / CELL_F)
#define R2CUT     (1.05e-3f * 1.05e-3f)   // = (CELL/2)^2 coverage guarantee
#define RAD2      (1e-3f * 1e-3f)
#define BIG       3.402823466e+38f

__device__ unsigned long long g_head[HSIZE];   // (gen<<14)|idx ; stale gen = empty
__device__ int                g_next[NPTS];
__device__ long long          g_ckey[NPTS];
__device__ int                g_match;
__device__ int                g_bar  = 0;
__device__ int                g_exit = 0;
__device__ unsigned long long g_gen  = 1;      // bumped by last block each launch

__device__ __forceinline__ unsigned int cell_hash(int cx, int cy, int cz) {
    unsigned int h = (unsigned int)(cx * 73856093) ^
                     (unsigned int)(cy * 19349663) ^
                     (unsigned int)(cz * 83492791);
    return h & (HSIZE - 1);
}

__device__ __forceinline__ long long cell_key(int cx, int cy, int cz) {
    return (((long long)(cx + (1 << 20))) << 42) |
           (((long long)(cy + (1 << 20))) << 21) |
            ((long long)(cz + (1 << 20)));
}

__device__ __forceinline__ void grid_barrier(int target) {
    __syncthreads();
    if (threadIdx.x == 0) {
        __threadfence();
        atomicAdd(&g_bar, 1);
        while (*(volatile int*)&g_bar < target) { }
        __threadfence();
    }
    __syncthreads();
}

__global__ __launch_bounds__(THREADS)
void ml_fused_kernel(const float* __restrict__ src, const float* __restrict__ tgt,
                     float* __restrict__ out) {
    __shared__ int swarp[THREADS / 32];
    const int tid  = threadIdx.x;
    const int lane = tid & 31;
    const int warp = tid >> 5;
    const int g    = blockIdx.x * THREADS + tid;   // 0..65535
    const int q    = g >> 2;                        // src index, 4 lanes each
    const int half = g & 3;                         // probe-group 0..3

    const unsigned long long gen = g_gen;           // consistent: set pre-launch

    // ---- Insert tgt points (one lane in four; no table clear needed) ----
    if (half == 0) {
        const float x = tgt[3 * q + 0], y = tgt[3 * q + 1], z = tgt[3 * q + 2];
        const int cx = (int)floorf(x * INV_CELL);
        const int cy = (int)floorf(y * INV_CELL);
        const int cz = (int)floorf(z * INV_CELL);
        g_ckey[q] = cell_key(cx, cy, cz);
        const unsigned long long old =
            atomicExch(&g_head[cell_hash(cx, cy, cz)],
                       (gen << 14) | (unsigned long long)q);
        g_next[q] = ((old >> 14) == gen) ? (int)(old & 16383ULL) : -1;
    }
    if (g == 0) g_match = 0;

    // ---- Pre-barrier: all src-side setup (overlaps barrier latency) ----
    const float px = src[3 * q + 0], py = src[3 * q + 1], pz = src[3 * q + 2];
    const float fx = px * INV_CELL, fy = py * INV_CELL, fz = pz * INV_CELL;
    const int cx = (int)floorf(fx);
    const int cy = (int)floorf(fy);
    const int cz = (int)floorf(fz);
    // base corner of the 2x2x2 block containing the radius ball
    const int bx = cx + ((fx - (float)cx >= 0.5f) ? 0 : -1);
    const int by = cy + ((fy - (float)cy >= 0.5f) ? 0 : -1);
    const int bz = cz + ((fz - (float)cz >= 0.5f) ? 0 : -1);

    // This lane's 2 of the 8 probe cells: p = half*2 + j, bits (x,y,z)
    long long    pkeys[2];
    unsigned int phash[2];
    #pragma unroll
    for (int j = 0; j < 2; ++j) {
        const int p   = half * 2 + j;
        const int ccx = bx + (p >> 2);
        const int ccy = by + ((p >> 1) & 1);
        const int ccz = bz + (p & 1);
        pkeys[j] = cell_key(ccx, ccy, ccz);
        phash[j] = cell_hash(ccx, ccy, ccz);
    }

    grid_barrier(NB);

    // ---- Query: 2 batched head loads, then (usually empty) chain walks ----
    unsigned long long h0 = g_head[phash[0]];
    unsigned long long h1 = g_head[phash[1]];

    float d1 = BIG, d2 = BIG;
    #pragma unroll
    for (int j = 0; j < 2; ++j) {
        const unsigned long long hw = j ? h1 : h0;
        int e = ((hw >> 14) == gen) ? (int)(hw & 16383ULL) : -1;
        while (e >= 0) {
            if (g_ckey[e] == pkeys[j]) {
                const float ex = px - tgt[3 * e + 0];
                const float ey = py - tgt[3 * e + 1];
                const float ez = pz - tgt[3 * e + 2];
                const float dd = fmaf(ex, ex, fmaf(ey, ey, ez * ez));
                d2 = fminf(d2, fmaxf(d1, dd));
                d1 = fminf(d1, dd);
            }
            e = g_next[e];
        }
    }

    // Merge top-2 values across the 4 lanes of this src point
    #pragma unroll
    for (int o = 1; o <= 2; o <<= 1) {
        const float o1 = __shfl_xor_sync(0xFFFFFFFFu, d1, o);
        const float o2 = __shfl_xor_sync(0xFFFFFFFFu, d2, o);
        d2 = fminf(fmaxf(d1, o1), fminf(d2, o2));
        d1 = fminf(d1, o1);
    }

    int m = 0;
    if (half == 0 && d2 <= R2CUT) {
        // Rare exact fallback: rescan the 8 cells tracking coords, apply the
        // reference pd test (componentwise +1e-6 before the norm).
        float e1 = BIG, e2 = BIG;
        float q1x = 0, q1y = 0, q1z = 0, q2x = 0, q2y = 0, q2z = 0;
        for (int p = 0; p < 8; ++p) {
            const int ccx = bx + (p >> 2);
            const int ccy = by + ((p >> 1) & 1);
            const int ccz = bz + (p & 1);
            const long long pk = cell_key(ccx, ccy, ccz);
            unsigned long long hw = g_head[cell_hash(ccx, ccy, ccz)];
            int e = ((hw >> 14) == gen) ? (int)(hw & 16383ULL) : -1;
            while (e >= 0) {
                if (g_ckey[e] == pk) {
                    const float tx = tgt[3 * e + 0], ty = tgt[3 * e + 1], tz = tgt[3 * e + 2];
                    const float ex = px - tx, ey = py - ty, ez = pz - tz;
                    const float dd = fmaf(ex, ex, fmaf(ey, ey, ez * ez));
                    if (dd < e2) {
                        if (dd < e1) {
                            e2 = e1; q2x = q1x; q2y = q1y; q2z = q1z;
                            e1 = dd; q1x = tx;  q1y = ty;  q1z = tz;
                        } else {
                            e2 = dd; q2x = tx; q2y = ty; q2z = tz;
                        }
                    }
                }
                e = g_next[e];
            }
        }
        if (e2 <= R2CUT) {
            const float ex = px - q2x + 1e-6f;
            const float ey = py - q2y + 1e-6f;
            const float ez = pz - q2z + 1e-6f;
            if (fmaf(ex, ex, fmaf(ey, ey, ez * ez)) < RAD2) m = 1;
        }
    }

    // Deterministic integer reduction; one atomic per block
    #pragma unroll
    for (int o = 16; o > 0; o >>= 1)
        m += __shfl_down_sync(0xFFFFFFFFu, m, o);
    if (lane == 0) swarp[warp] = m;
    __syncthreads();

    if (tid == 0) {
        int bs = 0;
        #pragma unroll
        for (int w = 0; w < THREADS / 32; ++w) bs += swarp[w];
        if (bs) atomicAdd(&g_match, bs);
        __threadfence();
        // Last block to exit finalizes and restores state for graph replay.
        const int e = atomicAdd(&g_exit, 1);
        if (e == NB - 1) {
            const int mm = *(volatile int*)&g_match;
            const float S = (float)(NPTS - mm) * expf(EPS_F)
                          + (float)mm * expf(1.0f + EPS_F);
            out[0] = logf(1.0f + S);   // softplus(logsumexp(mv))
            g_bar  = 0;
            g_exit = 0;
            g_gen  = gen + 1;          // invalidates all buckets for next launch
            __threadfence();
        }
    }
}

extern "C" void kernel_launch(void* const* d_in, const int* in_sizes, int n_in,
                              void* d_out, int out_size) {
    const float* src = (const float*)d_in[0];  // src_coords [16384, 3]
    const float* tgt = (const float*)d_in[1];  // tgt_coords [16384, 3]
    float* out = (float*)d_out;
    ml_fused_kernel<<<NB, THREADS>>>(src, tgt, out);
}